// round 8
// baseline (speedup 1.0000x reference)
#include <cstdint>
#include <cuda_runtime.h>
#include <cuda_bf16.h>
#include <mma.h>

using namespace nvcuda;

#define BB 128
#define SS 256
#define DD 512
#define HH 1024
#define NCC 128
#define NCTA_REC 128

// ---------------- device scratch ----------------
__device__ float          g_P[(size_t)SS * BB * 4096];      // input-side preacts (no bias)
__device__ __align__(128) unsigned char g_hT2[2][HH * 256]; // transposed+swizzled h: [u][b] bf16, 256B/row
__device__ float          g_hf[BB * HH];                    // final hidden state
__device__ unsigned       g_cnt = 0;
__device__ unsigned       g_gen = 0;
__device__ __nv_bfloat16  g_embb[(NCC + 1) * DD];           // bf16 embedding
__device__ __nv_bfloat16  g_Wxb[4][(size_t)DD * HH];        // bf16 input weights

__device__ __forceinline__ float sigm(float v) { return 1.0f / (1.0f + expf(-v)); }

__device__ __forceinline__ void cp16(unsigned int dst, const void* src) {
    asm volatile("cp.async.cg.shared.global [%0], [%1], 16;\n" :: "r"(dst), "l"(src));
}
__device__ __forceinline__ void cp_commit() { asm volatile("cp.async.commit_group;\n"); }
template <int N> __device__ __forceinline__ void cp_wait() {
    asm volatile("cp.async.wait_group %0;\n" :: "n"(N));
}

// mbarrier helpers
__device__ __forceinline__ void mbar_init(unsigned mbar, unsigned cnt) {
    asm volatile("mbarrier.init.shared.b64 [%0], %1;" :: "r"(mbar), "r"(cnt) : "memory");
}
__device__ __forceinline__ void mbar_expect(unsigned mbar, unsigned bytes) {
    asm volatile("mbarrier.arrive.expect_tx.shared.b64 _, [%0], %1;" :: "r"(mbar), "r"(bytes) : "memory");
}
__device__ __forceinline__ void mbar_wait(unsigned mbar, unsigned phase) {
    asm volatile(
        "{\n\t.reg .pred P1;\n\t"
        "LAB_WAIT_%=:\n\t"
        "mbarrier.try_wait.parity.shared.b64 P1, [%0], %1;\n\t"
        "@P1 bra.uni DONE_%=;\n\t"
        "bra.uni LAB_WAIT_%=;\n\t"
        "DONE_%=:\n\t}"
        :: "r"(mbar), "r"(phase) : "memory");
}
__device__ __forceinline__ void bulk_g2s(unsigned dst, const void* src, unsigned bytes, unsigned mbar) {
    asm volatile("cp.async.bulk.shared::cluster.global.mbarrier::complete_tx::bytes [%0], [%1], %2, [%3];"
                 :: "r"(dst), "l"(src), "r"(bytes), "r"(mbar) : "memory");
}

// Sense-reversing grid barrier (atomic arrivals; last arrival releases)
__device__ __forceinline__ void gridbar()
{
    __syncthreads();
    if (threadIdx.x == 0) {
        __threadfence();
        volatile unsigned* gen = &g_gen;
        unsigned g0 = *gen;
        unsigned arr = atomicAdd(&g_cnt, 1u);
        if (arr == NCTA_REC - 1) {
            g_cnt = 0;
            __threadfence();
            *gen = g0 + 1u;
        } else {
            while (*gen == g0) { }
        }
    }
    __syncthreads();
    __threadfence();
}

// ======================================================================
// Kernel 0: one-time f32 -> bf16 conversion of emb and the 4 input weights
// ======================================================================
__global__ __launch_bounds__(256) void k_convert(
    const float* __restrict__ emb,
    const float* __restrict__ W0, const float* __restrict__ W1,
    const float* __restrict__ W2, const float* __restrict__ W3)
{
    const float* Wsrc[4] = { W0, W1, W2, W3 };
    size_t tid    = (size_t)blockIdx.x * blockDim.x + threadIdx.x;
    size_t stride = (size_t)gridDim.x * blockDim.x;
    const size_t nW4 = (size_t)DD * HH / 4;
    for (size_t e = tid; e < 4 * nW4; e += stride) {
        int g = (int)(e / nW4);
        size_t o = (e % nW4) * 4;
        float4 v = *(const float4*)(Wsrc[g] + o);
        __nv_bfloat16* d = &g_Wxb[g][o];
        d[0] = __float2bfloat16(v.x); d[1] = __float2bfloat16(v.y);
        d[2] = __float2bfloat16(v.z); d[3] = __float2bfloat16(v.w);
    }
    const size_t nE4 = (size_t)(NCC + 1) * DD / 4;
    for (size_t e = tid; e < nE4; e += stride) {
        float4 v = *(const float4*)(emb + e * 4);
        __nv_bfloat16* d = &g_embb[e * 4];
        d[0] = __float2bfloat16(v.x); d[1] = __float2bfloat16(v.y);
        d[2] = __float2bfloat16(v.z); d[3] = __float2bfloat16(v.w);
    }
}

// ======================================================================
// Kernel 1: input projections (double-buffered cp.async + wmma)
// ======================================================================
#define AS_LD 56
#define BS_LD 152

__global__ __launch_bounds__(256) void k_input_proj(const int* __restrict__ x)
{
    __shared__ __align__(16) __nv_bfloat16 As[2][128 * AS_LD];
    __shared__ __align__(16) __nv_bfloat16 Bs[2][32 * BS_LD];
    __shared__ int rowidx[128];

    const int t = threadIdx.x, w = t >> 5;
    const int tn = blockIdx.x, tm = blockIdx.y;
    const int n0 = tn * 128, gate = n0 >> 10, h0 = n0 & 1023;
    const __nv_bfloat16* Wb = g_Wxb[gate];

    if (t < 128) {
        int m = tm * 128 + t;
        int s = m >> 7, b = m & 127;
        rowidx[t] = x[b * SS + s];
    }
    __syncthreads();

    auto issue = [&](int it) {
        int kt = it * 32;
        unsigned int Aa = (unsigned int)__cvta_generic_to_shared(As[it & 1]);
        unsigned int Ba = (unsigned int)__cvta_generic_to_shared(Bs[it & 1]);
#pragma unroll
        for (int i = 0; i < 2; i++) {
            int e = t + i * 256, r = e >> 2, seg = e & 3;
            cp16(Aa + (r * AS_LD + seg * 8) * 2,
                 g_embb + (size_t)rowidx[r] * DD + kt + seg * 8);
        }
#pragma unroll
        for (int i = 0; i < 2; i++) {
            int e = t + i * 256, r = e >> 4, seg = e & 15;
            cp16(Ba + (r * BS_LD + seg * 8) * 2,
                 Wb + (size_t)(kt + r) * HH + h0 + seg * 8);
        }
    };

    wmma::fragment<wmma::accumulator, 16, 16, 16, float> acc[8];
#pragma unroll
    for (int i = 0; i < 8; i++) wmma::fill_fragment(acc[i], 0.0f);

    issue(0); cp_commit();
    for (int it = 0; it < 16; it++) {
        if (it < 15) issue(it + 1);
        cp_commit();
        cp_wait<1>();
        __syncthreads();
        const __nv_bfloat16* A = As[it & 1];
        const __nv_bfloat16* B = Bs[it & 1];
#pragma unroll
        for (int ks = 0; ks < 2; ks++) {
            wmma::fragment<wmma::matrix_a, 16, 16, 16, __nv_bfloat16, wmma::row_major> af;
            wmma::load_matrix_sync(af, A + (w * 16) * AS_LD + ks * 16, AS_LD);
#pragma unroll
            for (int nb = 0; nb < 8; nb++) {
                wmma::fragment<wmma::matrix_b, 16, 16, 16, __nv_bfloat16, wmma::row_major> bfr;
                wmma::load_matrix_sync(bfr, B + (ks * 16) * BS_LD + nb * 16, BS_LD);
                wmma::mma_sync(acc[nb], af, bfr, acc[nb]);
            }
        }
        __syncthreads();
    }

    size_t base = (size_t)(tm * 128 + w * 16) * 4096 + n0;
#pragma unroll
    for (int nb = 0; nb < 8; nb++)
        wmma::store_matrix_sync(g_P + base + nb * 16, acc[nb], 4096, wmma::mem_row_major);
}

// ======================================================================
// Kernel 2: persistent recurrent scan. 128 CTAs x 8 hidden units, 128 threads.
// 4 warps, m=32 rows each (halves B-fragment SMEM traffic vs 8x m=16).
// h transposed+swizzled in global, bulk-copied 2x64KB double-buffered.
// Epilogue: thread t owns batch row b=t, C state in registers.
// ======================================================================
#define WS_LD 1032
#define CHUNK_B 65536

#define SM_MBAR   0
#define SM_ABUF   1024
#define SM_WS     (SM_ABUF + 2 * CHUNK_B)      // 132096
#define SM_SG     (SM_WS + 32 * WS_LD * 2)     // 198144
#define SM_TOT    (SM_SG + 128 * 36 * 4)       // 216576

__global__ void __launch_bounds__(128, 1) k_recur(
    const int*   __restrict__ x,
    const float* __restrict__ Wfh, const float* __restrict__ Wih,
    const float* __restrict__ Wgh, const float* __restrict__ Woh,
    const float* __restrict__ bfp, const float* __restrict__ bip,
    const float* __restrict__ bgp, const float* __restrict__ bop)
{
    extern __shared__ __align__(1024) unsigned char dyn[];
    __nv_bfloat16* Ws = (__nv_bfloat16*)(dyn + SM_WS);
    float*         Sg = (float*)(dyn + SM_SG);

    const unsigned smem0 = (unsigned)__cvta_generic_to_shared(dyn);
    const unsigned mb[2]   = { smem0 + SM_MBAR, smem0 + SM_MBAR + 8 };
    const unsigned Abuf[2] = { smem0 + SM_ABUF, smem0 + SM_ABUF + CHUNK_B };

    const int t = threadIdx.x, w = t >> 5, l = t & 31;
    const int c = blockIdx.x, u0 = c * 8;
    const float* Wg[4] = { Wfh, Wih, Wgh, Woh };

    if (t == 0) { mbar_init(mb[0], 1); mbar_init(mb[1], 1); }
    asm volatile("fence.proxy.async.shared::cta;" ::: "memory");

    // weight slice -> SMEM (bf16, col-major, padded stride)
    for (int e = t; e < 32 * 1024; e += 128) {
        int k = e >> 5, col = e & 31, g = col >> 3, j = col & 7;
        Ws[col * WS_LD + k] = __float2bfloat16(Wg[g][(size_t)k * HH + u0 + j]);
    }
    // zero own 8 rows of hT buffer 0 (8 rows x 256B; 128 threads x 16B)
    *(uint4*)(g_hT2[0] + (u0 + (t >> 4)) * 256 + (t & 15) * 16) = make_uint4(0, 0, 0, 0);

    // biases in registers (thread owns b=t, units u0..u0+7)
    float bias[4][8];
#pragma unroll
    for (int g = 0; g < 4; g++) {
        const float* bsrc = (g == 0) ? bfp : (g == 1) ? bip : (g == 2) ? bgp : bop;
        *(float4*)&bias[g][0] = *(const float4*)(bsrc + u0);
        *(float4*)&bias[g][4] = *(const float4*)(bsrc + u0 + 4);
    }
    float C[8];
#pragma unroll
    for (int j = 0; j < 8; j++) C[j] = 0.0f;

    // ldmatrix lane constants
    const unsigned a_sw0  = (((unsigned)(4 * w +     ((l >> 3) & 1)) ^ (unsigned)(l & 7)) << 4);
    const unsigned a_sw1  = (((unsigned)(4 * w + 2 + ((l >> 3) & 1)) ^ (unsigned)(l & 7)) << 4);
    const int      a_krow = (l & 7) + ((l >> 4) & 1) * 8;
    const unsigned bbase  = smem0 + SM_WS + ((l & 7) + ((l >> 4) & 1) * 8) * (WS_LD * 2) + ((l >> 3) & 1) * 16;

    // h-store swizzled offsets (thread t = batch row, 8 unit-rows)
    const unsigned blo = (unsigned)(t & 7) * 2, bhi = (unsigned)(t >> 3);

    __syncthreads();
    gridbar();   // zeros + mbarriers ready everywhere

    for (int s = 0; s < SS; s++) {
        const unsigned char* hsrc = g_hT2[s & 1];
        unsigned char*       hdst = g_hT2[(s + 1) & 1];

        if (t == 0) {
            mbar_expect(mb[0], CHUNK_B);
            bulk_g2s(Abuf[0], hsrc + 0 * CHUNK_B, CHUNK_B, mb[0]);
            mbar_expect(mb[1], CHUNK_B);
            bulk_g2s(Abuf[1], hsrc + 1 * CHUNK_B, CHUNK_B, mb[1]);
        }

        // prefetch input-side preacts + reset mask (independent of h)
        float pf[4][8];
        {
            const float* Pb = g_P + ((size_t)(s * BB + t)) * 4096 + u0;
#pragma unroll
            for (int g = 0; g < 4; g++) {
                *(float4*)&pf[g][0] = *(const float4*)(Pb + g * 1024);
                *(float4*)&pf[g][4] = *(const float4*)(Pb + g * 1024 + 4);
            }
        }
        const float rmask = (x[t * SS + s] > 0) ? 1.0f : 0.0f;

        float accA[16], accB[16];
#pragma unroll
        for (int i = 0; i < 16; i++) { accA[i] = 0.0f; accB[i] = 0.0f; }

        for (int kc = 0; kc < 4; kc++) {
            mbar_wait(mb[kc & 1], (kc >> 1) & 1);
            const unsigned Ab = Abuf[kc & 1];
#pragma unroll
            for (int kt = 0; kt < 16; kt++) {
                unsigned arow = Ab + (unsigned)((kt * 16 + a_krow) * 256);
                unsigned a0, a1, a2, a3, a4, a5, a6, a7;
                asm volatile("ldmatrix.sync.aligned.m8n8.x4.trans.shared.b16 {%0,%1,%2,%3}, [%4];"
                             : "=r"(a0), "=r"(a1), "=r"(a2), "=r"(a3) : "r"(arow + a_sw0));
                asm volatile("ldmatrix.sync.aligned.m8n8.x4.trans.shared.b16 {%0,%1,%2,%3}, [%4];"
                             : "=r"(a4), "=r"(a5), "=r"(a6), "=r"(a7) : "r"(arow + a_sw1));
                unsigned baddr = bbase + (unsigned)((kc * 16 + kt) * 32);
                unsigned b0, b1, b2, b3, b4, b5, b6, b7;
                asm volatile("ldmatrix.sync.aligned.m8n8.x4.shared.b16 {%0,%1,%2,%3}, [%4];"
                             : "=r"(b0), "=r"(b1), "=r"(b2), "=r"(b3) : "r"(baddr));
                asm volatile("ldmatrix.sync.aligned.m8n8.x4.shared.b16 {%0,%1,%2,%3}, [%4];"
                             : "=r"(b4), "=r"(b5), "=r"(b6), "=r"(b7) : "r"(baddr + 16u * (WS_LD * 2)));

#define MMA4(ACC, O, A0, A1, A2, A3, B0, B1) \
                asm volatile("mma.sync.aligned.m16n8k16.row.col.f32.bf16.bf16.f32 " \
                             "{%0,%1,%2,%3}, {%4,%5,%6,%7}, {%8,%9}, {%0,%1,%2,%3};" \
                             : "+f"(ACC[O]), "+f"(ACC[O+1]), "+f"(ACC[O+2]), "+f"(ACC[O+3]) \
                             : "r"(A0), "r"(A1), "r"(A2), "r"(A3), "r"(B0), "r"(B1))
                MMA4(accA, 0,  a0, a1, a2, a3, b0, b1);
                MMA4(accA, 4,  a0, a1, a2, a3, b2, b3);
                MMA4(accA, 8,  a0, a1, a2, a3, b4, b5);
                MMA4(accA, 12, a0, a1, a2, a3, b6, b7);
                MMA4(accB, 0,  a4, a5, a6, a7, b0, b1);
                MMA4(accB, 4,  a4, a5, a6, a7, b2, b3);
                MMA4(accB, 8,  a4, a5, a6, a7, b4, b5);
                MMA4(accB, 12, a4, a5, a6, a7, b6, b7);
#undef MMA4
            }
            __syncthreads();   // all warps done reading this buffer
            if (t == 0 && kc < 2) {
                mbar_expect(mb[kc & 1], CHUNK_B);
                bulk_g2s(Abuf[kc & 1], hsrc + (kc + 2) * CHUNK_B, CHUNK_B, mb[kc & 1]);
            }
        }

        // store C-fragments to Sg [128 m][36 stride]
        {
            int mr = w * 32 + (l >> 2);
            int col = 2 * (l & 3);
#pragma unroll
            for (int nt = 0; nt < 4; nt++) {
                *(float2*)&Sg[mr * 36 + nt * 8 + col]        = make_float2(accA[nt * 4 + 0], accA[nt * 4 + 1]);
                *(float2*)&Sg[(mr + 8) * 36 + nt * 8 + col]  = make_float2(accA[nt * 4 + 2], accA[nt * 4 + 3]);
                *(float2*)&Sg[(mr + 16) * 36 + nt * 8 + col] = make_float2(accB[nt * 4 + 0], accB[nt * 4 + 1]);
                *(float2*)&Sg[(mr + 24) * 36 + nt * 8 + col] = make_float2(accB[nt * 4 + 2], accB[nt * 4 + 3]);
            }
        }
        __syncthreads();

        // gate epilogue: thread t owns batch row b=t, units u0..u0+7
        float hv[8];
        {
            float S[4][8];
#pragma unroll
            for (int g = 0; g < 4; g++) {
                *(float4*)&S[g][0] = *(float4*)&Sg[t * 36 + g * 8];
                *(float4*)&S[g][4] = *(float4*)&Sg[t * 36 + g * 8 + 4];
            }
#pragma unroll
            for (int j = 0; j < 8; j++) {
                float f  = sigm(pf[0][j] + bias[0][j] + S[0][j]);
                float ii = sigm(pf[1][j] + bias[1][j] + S[1][j]);
                float gg = sigm(pf[2][j] + bias[2][j] + S[2][j]);
                float oo = sigm(pf[3][j] + bias[3][j] + S[3][j]);
                C[j] = (gg * ii + C[j] * f) * rmask;
                hv[j] = oo * tanhf(C[j]);
            }
        }
        // swizzled transposed store: byte = u*256 + ((b>>3)^(u&7))*16 + (b&7)*2
#pragma unroll
        for (int j = 0; j < 8; j++) {
            unsigned u = (unsigned)(u0 + j);
            *(__nv_bfloat16*)(hdst + u * 256 + ((bhi ^ (u & 7)) << 4) + blo) = __float2bfloat16(hv[j]);
        }
        if (s == SS - 1) {
            *(float4*)(g_hf + t * HH + u0)     = make_float4(hv[0], hv[1], hv[2], hv[3]);
            *(float4*)(g_hf + t * HH + u0 + 4) = make_float4(hv[4], hv[5], hv[6], hv[7]);
        }

        if (s < SS - 1) gridbar();
    }
}

// ======================================================================
// Kernel 3: logits + log_softmax (256 thr, split-K x2, 4 accums — R5 best)
// ======================================================================
__global__ __launch_bounds__(256) void k_final(
    const float* __restrict__ Wph, const float* __restrict__ bp,
    float* __restrict__ out)
{
    __shared__ float h[HH];
    __shared__ float part[NCC];
    __shared__ float red[NCC];
    const int b = blockIdx.x, t = threadIdx.x;
    const int cls = t & 127, half = t >> 7;

    for (int i = t; i < HH; i += 256) h[i] = g_hf[b * HH + i];
    __syncthreads();

    const float* W = Wph + (size_t)(half * 512) * NCC + cls;
    const float* hh = h + half * 512;
    float a0 = 0.f, a1 = 0.f, a2 = 0.f, a3 = 0.f;
#pragma unroll 8
    for (int k = 0; k < 512; k += 4) {
        a0 += hh[k + 0] * W[(size_t)(k + 0) * NCC];
        a1 += hh[k + 1] * W[(size_t)(k + 1) * NCC];
        a2 += hh[k + 2] * W[(size_t)(k + 2) * NCC];
        a3 += hh[k + 3] * W[(size_t)(k + 3) * NCC];
    }
    float p = (a0 + a1) + (a2 + a3);
    if (half) part[cls] = p;
    __syncthreads();

    if (half == 0) p += part[cls] + bp[cls];

    if (t < 128) red[t] = p;
    __syncthreads();
    for (int off = 64; off; off >>= 1) {
        if (t < off) red[t] = fmaxf(red[t], red[t + off]);
        __syncthreads();
    }
    float m = red[0]; __syncthreads();
    if (t < 128) red[t] = expf(p - m);
    __syncthreads();
    for (int off = 64; off; off >>= 1) {
        if (t < off) red[t] += red[t + off];
        __syncthreads();
    }
    if (t < 128) {
        float lse = m + logf(red[0]);
        out[b * NCC + t] = p - lse;
    }
}

// ======================================================================
extern "C" void kernel_launch(void* const* d_in, const int* in_sizes, int n_in,
                              void* d_out, int out_size)
{
    const int*   x   = (const int*)  d_in[0];
    const float* emb = (const float*)d_in[1];
    const float* Wfx = (const float*)d_in[2];
    const float* Wfh = (const float*)d_in[3];
    const float* bf  = (const float*)d_in[4];
    const float* Wix = (const float*)d_in[5];
    const float* Wih = (const float*)d_in[6];
    const float* bi  = (const float*)d_in[7];
    const float* Wgx = (const float*)d_in[8];
    const float* Wgh = (const float*)d_in[9];
    const float* bg  = (const float*)d_in[10];
    const float* Wox = (const float*)d_in[11];
    const float* Woh = (const float*)d_in[12];
    const float* bo  = (const float*)d_in[13];
    const float* Wph = (const float*)d_in[14];
    const float* bp  = (const float*)d_in[15];
    float* out = (float*)d_out;

    static bool attr_set = false;
    if (!attr_set) {
        cudaFuncSetAttribute(k_recur, cudaFuncAttributeMaxDynamicSharedMemorySize, SM_TOT);
        attr_set = true;
    }

    // 0) bf16 pre-conversion
    k_convert<<<512, 256>>>(emb, Wfx, Wix, Wgx, Wox);

    // 1) input-side projections
    dim3 g1(4096 / 128, (SS * BB) / 128);
    k_input_proj<<<g1, 256>>>(x);

    // 2) persistent recurrent scan
    k_recur<<<NCTA_REC, 128, SM_TOT>>>(x, Wfh, Wih, Wgh, Woh, bf, bi, bg, bo);

    // 3) final projection + log_softmax
    k_final<<<BB, 256>>>(Wph, bp, out);
}

// round 9
// speedup vs baseline: 1.0190x; 1.0190x over previous
#include <cstdint>
#include <cuda_runtime.h>
#include <cuda_bf16.h>
#include <mma.h>

using namespace nvcuda;

#define BB 128
#define SS 256
#define DD 512
#define HH 1024
#define NCC 128
#define NCTA_REC 256   // 2 CTAs per SM; each owns 4 hidden units (16 gate cols)

// ---------------- device scratch ----------------
__device__ float          g_P[(size_t)SS * BB * 4096];      // input-side preacts (no bias)
__device__ __align__(128) unsigned char g_hT2[2][HH * 256]; // transposed+swizzled h: [u][b] bf16, 256B/row
__device__ float          g_hf[BB * HH];                    // final hidden state
__device__ unsigned       g_cnt = 0;                        // init barrier
__device__ unsigned       g_gen = 0;
__device__ unsigned       g_bar8[8 * 32];                   // per-chunk-group counters (128B lines)
__device__ __nv_bfloat16  g_embb[(NCC + 1) * DD];           // bf16 embedding
__device__ __nv_bfloat16  g_Wxb[4][(size_t)DD * HH];        // bf16 input weights

__device__ __forceinline__ float sigm(float v) { return 1.0f / (1.0f + expf(-v)); }

__device__ __forceinline__ void cp16(unsigned int dst, const void* src) {
    asm volatile("cp.async.cg.shared.global [%0], [%1], 16;\n" :: "r"(dst), "l"(src));
}
__device__ __forceinline__ void cp_commit() { asm volatile("cp.async.commit_group;\n"); }
template <int N> __device__ __forceinline__ void cp_wait() {
    asm volatile("cp.async.wait_group %0;\n" :: "n"(N));
}
__device__ __forceinline__ unsigned ld_acq(const unsigned* p) {
    unsigned v;
    asm volatile("ld.acquire.gpu.global.u32 %0, [%1];" : "=r"(v) : "l"(p) : "memory");
    return v;
}

// mbarrier helpers
__device__ __forceinline__ void mbar_init(unsigned mbar, unsigned cnt) {
    asm volatile("mbarrier.init.shared.b64 [%0], %1;" :: "r"(mbar), "r"(cnt) : "memory");
}
__device__ __forceinline__ void mbar_expect(unsigned mbar, unsigned bytes) {
    asm volatile("mbarrier.arrive.expect_tx.shared.b64 _, [%0], %1;" :: "r"(mbar), "r"(bytes) : "memory");
}
__device__ __forceinline__ void mbar_wait(unsigned mbar, unsigned phase) {
    asm volatile(
        "{\n\t.reg .pred P1;\n\t"
        "LAB_WAIT_%=:\n\t"
        "mbarrier.try_wait.parity.shared.b64 P1, [%0], %1;\n\t"
        "@P1 bra.uni DONE_%=;\n\t"
        "bra.uni LAB_WAIT_%=;\n\t"
        "DONE_%=:\n\t}"
        :: "r"(mbar), "r"(phase) : "memory");
}
__device__ __forceinline__ void bulk_g2s(unsigned dst, const void* src, unsigned bytes, unsigned mbar) {
    asm volatile("cp.async.bulk.shared::cluster.global.mbarrier::complete_tx::bytes [%0], [%1], %2, [%3];"
                 :: "r"(dst), "l"(src), "r"(bytes), "r"(mbar) : "memory");
}

// init-time grid barrier (atomic; used once per launch)
__device__ __forceinline__ void gridbar()
{
    __syncthreads();
    if (threadIdx.x == 0) {
        __threadfence();
        volatile unsigned* gen = &g_gen;
        unsigned g0 = *gen;
        unsigned arr = atomicAdd(&g_cnt, 1u);
        if (arr == NCTA_REC - 1) {
            g_cnt = 0;
            __threadfence();
            *gen = g0 + 1u;
        } else {
            while (*gen == g0) { }
        }
    }
    __syncthreads();
    __threadfence();
}

// ======================================================================
// Kernel 0: one-time f32 -> bf16 conversion of emb and the 4 input weights
// ======================================================================
__global__ __launch_bounds__(256) void k_convert(
    const float* __restrict__ emb,
    const float* __restrict__ W0, const float* __restrict__ W1,
    const float* __restrict__ W2, const float* __restrict__ W3)
{
    const float* Wsrc[4] = { W0, W1, W2, W3 };
    size_t tid    = (size_t)blockIdx.x * blockDim.x + threadIdx.x;
    size_t stride = (size_t)gridDim.x * blockDim.x;
    const size_t nW4 = (size_t)DD * HH / 4;
    for (size_t e = tid; e < 4 * nW4; e += stride) {
        int g = (int)(e / nW4);
        size_t o = (e % nW4) * 4;
        float4 v = *(const float4*)(Wsrc[g] + o);
        __nv_bfloat16* d = &g_Wxb[g][o];
        d[0] = __float2bfloat16(v.x); d[1] = __float2bfloat16(v.y);
        d[2] = __float2bfloat16(v.z); d[3] = __float2bfloat16(v.w);
    }
    const size_t nE4 = (size_t)(NCC + 1) * DD / 4;
    for (size_t e = tid; e < nE4; e += stride) {
        float4 v = *(const float4*)(emb + e * 4);
        __nv_bfloat16* d = &g_embb[e * 4];
        d[0] = __float2bfloat16(v.x); d[1] = __float2bfloat16(v.y);
        d[2] = __float2bfloat16(v.z); d[3] = __float2bfloat16(v.w);
    }
}

// ======================================================================
// Kernel 1: input projections (double-buffered cp.async + wmma) — R5 best
// ======================================================================
#define AS_LD 56
#define BS_LD 152

__global__ __launch_bounds__(256) void k_input_proj(const int* __restrict__ x)
{
    __shared__ __align__(16) __nv_bfloat16 As[2][128 * AS_LD];
    __shared__ __align__(16) __nv_bfloat16 Bs[2][32 * BS_LD];
    __shared__ int rowidx[128];

    const int t = threadIdx.x, w = t >> 5;
    const int tn = blockIdx.x, tm = blockIdx.y;
    const int n0 = tn * 128, gate = n0 >> 10, h0 = n0 & 1023;
    const __nv_bfloat16* Wb = g_Wxb[gate];

    if (t < 128) {
        int m = tm * 128 + t;
        int s = m >> 7, b = m & 127;
        rowidx[t] = x[b * SS + s];
    }
    __syncthreads();

    auto issue = [&](int it) {
        int kt = it * 32;
        unsigned int Aa = (unsigned int)__cvta_generic_to_shared(As[it & 1]);
        unsigned int Ba = (unsigned int)__cvta_generic_to_shared(Bs[it & 1]);
#pragma unroll
        for (int i = 0; i < 2; i++) {
            int e = t + i * 256, r = e >> 2, seg = e & 3;
            cp16(Aa + (r * AS_LD + seg * 8) * 2,
                 g_embb + (size_t)rowidx[r] * DD + kt + seg * 8);
        }
#pragma unroll
        for (int i = 0; i < 2; i++) {
            int e = t + i * 256, r = e >> 4, seg = e & 15;
            cp16(Ba + (r * BS_LD + seg * 8) * 2,
                 Wb + (size_t)(kt + r) * HH + h0 + seg * 8);
        }
    };

    wmma::fragment<wmma::accumulator, 16, 16, 16, float> acc[8];
#pragma unroll
    for (int i = 0; i < 8; i++) wmma::fill_fragment(acc[i], 0.0f);

    issue(0); cp_commit();
    for (int it = 0; it < 16; it++) {
        if (it < 15) issue(it + 1);
        cp_commit();
        cp_wait<1>();
        __syncthreads();
        const __nv_bfloat16* A = As[it & 1];
        const __nv_bfloat16* B = Bs[it & 1];
#pragma unroll
        for (int ks = 0; ks < 2; ks++) {
            wmma::fragment<wmma::matrix_a, 16, 16, 16, __nv_bfloat16, wmma::row_major> af;
            wmma::load_matrix_sync(af, A + (w * 16) * AS_LD + ks * 16, AS_LD);
#pragma unroll
            for (int nb = 0; nb < 8; nb++) {
                wmma::fragment<wmma::matrix_b, 16, 16, 16, __nv_bfloat16, wmma::row_major> bfr;
                wmma::load_matrix_sync(bfr, B + (ks * 16) * BS_LD + nb * 16, BS_LD);
                wmma::mma_sync(acc[nb], af, bfr, acc[nb]);
            }
        }
        __syncthreads();
    }

    size_t base = (size_t)(tm * 128 + w * 16) * 4096 + n0;
#pragma unroll
    for (int nb = 0; nb < 8; nb++)
        wmma::store_matrix_sync(g_P + base + nb * 16, acc[nb], 4096, wmma::mem_row_major);
}

// ======================================================================
// Kernel 2: persistent recurrent scan. 256 CTAs (2/SM) x 4 hidden units.
// 4 warps/CTA, m=32 rows each; N=16 gate cols.
// h transposed+swizzled in global; 8 x 32KB chunks, 2 buffers, TMA.
// Per-chunk-group counters (32 producers each) gate each chunk's TMA.
// ======================================================================
#define WS_LD 1032
#define CHUNK_B 32768

#define SM_MBAR   0
#define SM_ABUF   1024
#define SM_WS     (SM_ABUF + 2 * CHUNK_B)      // 66560
#define SM_SG     (SM_WS + 16 * WS_LD * 2)     // 99584
#define SM_TOT    (SM_SG + 128 * 20 * 4)       // 109824  (x2 CTA = 219648)

__global__ void __launch_bounds__(128) k_recur(
    const int*   __restrict__ x,
    const float* __restrict__ Wfh, const float* __restrict__ Wih,
    const float* __restrict__ Wgh, const float* __restrict__ Woh,
    const float* __restrict__ bfp, const float* __restrict__ bip,
    const float* __restrict__ bgp, const float* __restrict__ bop)
{
    extern __shared__ __align__(1024) unsigned char dyn[];
    __nv_bfloat16* Ws = (__nv_bfloat16*)(dyn + SM_WS);
    float*         Sg = (float*)(dyn + SM_SG);

    const unsigned smem0 = (unsigned)__cvta_generic_to_shared(dyn);
    const unsigned mb[2]   = { smem0 + SM_MBAR, smem0 + SM_MBAR + 8 };
    const unsigned Abuf[2] = { smem0 + SM_ABUF, smem0 + SM_ABUF + CHUNK_B };

    const int t = threadIdx.x, w = t >> 5, l = t & 31;
    const int c = blockIdx.x, u0 = c * 4;      // 4 hidden units per CTA
    const int grp = c >> 5;                    // producer group = h-chunk index
    const float* Wg[4] = { Wfh, Wih, Wgh, Woh };

    if (t == 0) { mbar_init(mb[0], 1); mbar_init(mb[1], 1); }
    asm volatile("fence.proxy.async.shared::cta;" ::: "memory");

    // counter bases (pre-arrival values; arrivals happen only after init gridbar)
    unsigned bar_base[8];
#pragma unroll
    for (int i = 0; i < 8; i++) bar_base[i] = *(volatile unsigned*)&g_bar8[i * 32];

    // weight slice -> SMEM: 16 cols (col = gate*4 + j), col-major, padded stride
    for (int e = t; e < 16 * 1024; e += 128) {
        int k = e >> 4, col = e & 15, g = col >> 2, j = col & 3;
        Ws[col * WS_LD + k] = __float2bfloat16(Wg[g][(size_t)k * HH + u0 + j]);
    }
    // zero own 4 rows of hT buffer 0 (4 x 256B = 64 x 16B)
    if (t < 64)
        *(uint4*)(g_hT2[0] + (u0 + (t >> 4)) * 256 + (t & 15) * 16) = make_uint4(0, 0, 0, 0);

    // biases in registers (thread owns b=t, units u0..u0+3)
    float bias[4][4];
#pragma unroll
    for (int g = 0; g < 4; g++) {
        const float* bsrc = (g == 0) ? bfp : (g == 1) ? bip : (g == 2) ? bgp : bop;
        *(float4*)&bias[g][0] = *(const float4*)(bsrc + u0);
    }
    float C[4] = { 0.f, 0.f, 0.f, 0.f };

    // ldmatrix lane constants (4 warps, m=32 per warp)
    const unsigned a_sw0  = (((unsigned)(4 * w +     ((l >> 3) & 1)) ^ (unsigned)(l & 7)) << 4);
    const unsigned a_sw1  = (((unsigned)(4 * w + 2 + ((l >> 3) & 1)) ^ (unsigned)(l & 7)) << 4);
    const int      a_krow = (l & 7) + ((l >> 4) & 1) * 8;
    const unsigned bbase  = smem0 + SM_WS + ((l & 7) + ((l >> 4) & 1) * 8) * (WS_LD * 2) + ((l >> 3) & 1) * 16;

    // h-store swizzled offsets (thread t = batch row)
    const unsigned blo = (unsigned)(t & 7) * 2, bhi = (unsigned)(t >> 3);

    __syncthreads();
    gridbar();   // zeros + SMEM + counter bases consistent everywhere

    for (int s = 0; s < SS; s++) {
        const unsigned char* hsrc = g_hT2[s & 1];
        unsigned char*       hdst = g_hT2[(s + 1) & 1];
        const unsigned       lvl  = (unsigned)s * 32u;

        // poll producer groups 0,1 then issue chunks 0,1
        if (t == 0) {
#pragma unroll
            for (int cc = 0; cc < 2; cc++) {
                unsigned tgt = bar_base[cc] + lvl;
                while ((int)(ld_acq(&g_bar8[cc * 32]) - tgt) < 0) { }
                mbar_expect(mb[cc], CHUNK_B);
                bulk_g2s(Abuf[cc], hsrc + cc * CHUNK_B, CHUNK_B, mb[cc]);
            }
        }

        // prefetch input-side preacts + reset mask (independent of h)
        float pf[4][4];
        {
            const float* Pb = g_P + ((size_t)(s * BB + t)) * 4096 + u0;
#pragma unroll
            for (int g = 0; g < 4; g++)
                *(float4*)&pf[g][0] = *(const float4*)(Pb + g * 1024);
        }
        const float rmask = (x[t * SS + s] > 0) ? 1.0f : 0.0f;

        float accA[8], accB[8];
#pragma unroll
        for (int i = 0; i < 8; i++) { accA[i] = 0.0f; accB[i] = 0.0f; }

        for (int kc = 0; kc < 8; kc++) {
            mbar_wait(mb[kc & 1], (kc >> 1) & 1);
            const unsigned Ab = Abuf[kc & 1];
#pragma unroll
            for (int kt = 0; kt < 8; kt++) {
                unsigned arow = Ab + (unsigned)((kt * 16 + a_krow) * 256);
                unsigned a0, a1, a2, a3, a4, a5, a6, a7;
                asm volatile("ldmatrix.sync.aligned.m8n8.x4.trans.shared.b16 {%0,%1,%2,%3}, [%4];"
                             : "=r"(a0), "=r"(a1), "=r"(a2), "=r"(a3) : "r"(arow + a_sw0));
                asm volatile("ldmatrix.sync.aligned.m8n8.x4.trans.shared.b16 {%0,%1,%2,%3}, [%4];"
                             : "=r"(a4), "=r"(a5), "=r"(a6), "=r"(a7) : "r"(arow + a_sw1));
                unsigned baddr = bbase + (unsigned)((kc * 8 + kt) * 32);
                unsigned b0, b1, b2, b3;
                asm volatile("ldmatrix.sync.aligned.m8n8.x4.shared.b16 {%0,%1,%2,%3}, [%4];"
                             : "=r"(b0), "=r"(b1), "=r"(b2), "=r"(b3) : "r"(baddr));

#define MMA4(ACC, O, A0, A1, A2, A3, B0, B1) \
                asm volatile("mma.sync.aligned.m16n8k16.row.col.f32.bf16.bf16.f32 " \
                             "{%0,%1,%2,%3}, {%4,%5,%6,%7}, {%8,%9}, {%0,%1,%2,%3};" \
                             : "+f"(ACC[O]), "+f"(ACC[O+1]), "+f"(ACC[O+2]), "+f"(ACC[O+3]) \
                             : "r"(A0), "r"(A1), "r"(A2), "r"(A3), "r"(B0), "r"(B1))
                MMA4(accA, 0, a0, a1, a2, a3, b0, b1);
                MMA4(accA, 4, a0, a1, a2, a3, b2, b3);
                MMA4(accB, 0, a4, a5, a6, a7, b0, b1);
                MMA4(accB, 4, a4, a5, a6, a7, b2, b3);
#undef MMA4
            }
            __syncthreads();   // all warps done reading this buffer
            if (t == 0 && kc < 6) {
                int nc = kc + 2;
                unsigned tgt = bar_base[nc] + lvl;
                while ((int)(ld_acq(&g_bar8[nc * 32]) - tgt) < 0) { }
                mbar_expect(mb[kc & 1], CHUNK_B);
                bulk_g2s(Abuf[kc & 1], hsrc + nc * CHUNK_B, CHUNK_B, mb[kc & 1]);
            }
        }

        // store C-fragments to Sg [128 m][20 stride]
        {
            int mr = w * 32 + (l >> 2);
            int col = 2 * (l & 3);
#pragma unroll
            for (int nt = 0; nt < 2; nt++) {
                *(float2*)&Sg[mr * 20 + nt * 8 + col]        = make_float2(accA[nt * 4 + 0], accA[nt * 4 + 1]);
                *(float2*)&Sg[(mr + 8) * 20 + nt * 8 + col]  = make_float2(accA[nt * 4 + 2], accA[nt * 4 + 3]);
                *(float2*)&Sg[(mr + 16) * 20 + nt * 8 + col] = make_float2(accB[nt * 4 + 0], accB[nt * 4 + 1]);
                *(float2*)&Sg[(mr + 24) * 20 + nt * 8 + col] = make_float2(accB[nt * 4 + 2], accB[nt * 4 + 3]);
            }
        }
        __syncthreads();

        // gate epilogue: thread t owns batch row b=t, units u0..u0+3
        float hv[4];
        {
            float S[4][4];
#pragma unroll
            for (int g = 0; g < 4; g++)
                *(float4*)&S[g][0] = *(float4*)&Sg[t * 20 + g * 4];
#pragma unroll
            for (int j = 0; j < 4; j++) {
                float f  = sigm(pf[0][j] + bias[0][j] + S[0][j]);
                float ii = sigm(pf[1][j] + bias[1][j] + S[1][j]);
                float gg = sigm(pf[2][j] + bias[2][j] + S[2][j]);
                float oo = sigm(pf[3][j] + bias[3][j] + S[3][j]);
                C[j] = (gg * ii + C[j] * f) * rmask;
                hv[j] = oo * tanhf(C[j]);
            }
        }
        // swizzled transposed store: byte = u*256 + ((b>>3)^(u&7))*16 + (b&7)*2
#pragma unroll
        for (int j = 0; j < 4; j++) {
            unsigned u = (unsigned)(u0 + j);
            *(__nv_bfloat16*)(hdst + u * 256 + ((bhi ^ (u & 7)) << 4) + blo) = __float2bfloat16(hv[j]);
        }
        if (s == SS - 1)
            *(float4*)(g_hf + t * HH + u0) = make_float4(hv[0], hv[1], hv[2], hv[3]);

        // publish: this CTA's 4 h-rows of step s+1 are complete
        __syncthreads();
        if (t == 0 && s < SS - 1) {
            __threadfence();
            atomicAdd(&g_bar8[grp * 32], 1u);
        }
    }
}

// ======================================================================
// Kernel 3: logits + log_softmax (256 thr, split-K x2, 4 accums — R5 best)
// ======================================================================
__global__ __launch_bounds__(256) void k_final(
    const float* __restrict__ Wph, const float* __restrict__ bp,
    float* __restrict__ out)
{
    __shared__ float h[HH];
    __shared__ float part[NCC];
    __shared__ float red[NCC];
    const int b = blockIdx.x, t = threadIdx.x;
    const int cls = t & 127, half = t >> 7;

    for (int i = t; i < HH; i += 256) h[i] = g_hf[b * HH + i];
    __syncthreads();

    const float* W = Wph + (size_t)(half * 512) * NCC + cls;
    const float* hh = h + half * 512;
    float a0 = 0.f, a1 = 0.f, a2 = 0.f, a3 = 0.f;
#pragma unroll 8
    for (int k = 0; k < 512; k += 4) {
        a0 += hh[k + 0] * W[(size_t)(k + 0) * NCC];
        a1 += hh[k + 1] * W[(size_t)(k + 1) * NCC];
        a2 += hh[k + 2] * W[(size_t)(k + 2) * NCC];
        a3 += hh[k + 3] * W[(size_t)(k + 3) * NCC];
    }
    float p = (a0 + a1) + (a2 + a3);
    if (half) part[cls] = p;
    __syncthreads();

    if (half == 0) p += part[cls] + bp[cls];

    if (t < 128) red[t] = p;
    __syncthreads();
    for (int off = 64; off; off >>= 1) {
        if (t < off) red[t] = fmaxf(red[t], red[t + off]);
        __syncthreads();
    }
    float m = red[0]; __syncthreads();
    if (t < 128) red[t] = expf(p - m);
    __syncthreads();
    for (int off = 64; off; off >>= 1) {
        if (t < off) red[t] += red[t + off];
        __syncthreads();
    }
    if (t < 128) {
        float lse = m + logf(red[0]);
        out[b * NCC + t] = p - lse;
    }
}

// ======================================================================
extern "C" void kernel_launch(void* const* d_in, const int* in_sizes, int n_in,
                              void* d_out, int out_size)
{
    const int*   x   = (const int*)  d_in[0];
    const float* emb = (const float*)d_in[1];
    const float* Wfx = (const float*)d_in[2];
    const float* Wfh = (const float*)d_in[3];
    const float* bf  = (const float*)d_in[4];
    const float* Wix = (const float*)d_in[5];
    const float* Wih = (const float*)d_in[6];
    const float* bi  = (const float*)d_in[7];
    const float* Wgx = (const float*)d_in[8];
    const float* Wgh = (const float*)d_in[9];
    const float* bg  = (const float*)d_in[10];
    const float* Wox = (const float*)d_in[11];
    const float* Woh = (const float*)d_in[12];
    const float* bo  = (const float*)d_in[13];
    const float* Wph = (const float*)d_in[14];
    const float* bp  = (const float*)d_in[15];
    float* out = (float*)d_out;

    static bool attr_set = false;
    if (!attr_set) {
        cudaFuncSetAttribute(k_recur, cudaFuncAttributeMaxDynamicSharedMemorySize, SM_TOT);
        attr_set = true;
    }

    // 0) bf16 pre-conversion
    k_convert<<<512, 256>>>(emb, Wfx, Wix, Wgx, Wox);

    // 1) input-side projections
    dim3 g1(4096 / 128, (SS * BB) / 128);
    k_input_proj<<<g1, 256>>>(x);

    // 2) persistent recurrent scan (256 CTAs, 2 per SM)
    k_recur<<<NCTA_REC, 128, SM_TOT>>>(x, Wfh, Wih, Wgh, Woh, bf, bi, bg, bo);

    // 3) final projection + log_softmax
    k_final<<<BB, 256>>>(Wph, bp, out);
}

// round 10
// speedup vs baseline: 1.2387x; 1.2156x over previous
#include <cstdint>
#include <cuda_runtime.h>
#include <cuda_bf16.h>
#include <mma.h>

using namespace nvcuda;

#define BB 128
#define SS 256
#define DD 512
#define HH 1024
#define NCC 128
#define NCTA_REC 128

// ---------------- device scratch ----------------
__device__ float          g_P[(size_t)SS * BB * 4096];      // input-side preacts (no bias)
__device__ __align__(128) unsigned char g_hT2[2][HH * 256]; // transposed+swizzled h: [u][b] bf16, 256B/row
__device__ float          g_hf[BB * HH];                    // final hidden state
__device__ unsigned       g_cnt = 0;                        // init barrier
__device__ unsigned       g_gen = 0;
__device__ unsigned       g_chk[8 * 32];                    // per-chunk producer counters (128B lines)
__device__ __nv_bfloat16  g_embb[(NCC + 1) * DD];           // bf16 embedding
__device__ __nv_bfloat16  g_Wxb[4][(size_t)DD * HH];        // bf16 input weights

__device__ __forceinline__ float sigm(float v) { return 1.0f / (1.0f + expf(-v)); }

__device__ __forceinline__ void cp16(unsigned int dst, const void* src) {
    asm volatile("cp.async.cg.shared.global [%0], [%1], 16;\n" :: "r"(dst), "l"(src));
}
__device__ __forceinline__ void cp_commit() { asm volatile("cp.async.commit_group;\n"); }
template <int N> __device__ __forceinline__ void cp_wait() {
    asm volatile("cp.async.wait_group %0;\n" :: "n"(N));
}
__device__ __forceinline__ unsigned ld_acq(const unsigned* p) {
    unsigned v;
    asm volatile("ld.acquire.gpu.global.u32 %0, [%1];" : "=r"(v) : "l"(p) : "memory");
    return v;
}

// mbarrier helpers
__device__ __forceinline__ void mbar_init(unsigned mbar, unsigned cnt) {
    asm volatile("mbarrier.init.shared.b64 [%0], %1;" :: "r"(mbar), "r"(cnt) : "memory");
}
__device__ __forceinline__ void mbar_expect(unsigned mbar, unsigned bytes) {
    asm volatile("mbarrier.arrive.expect_tx.shared.b64 _, [%0], %1;" :: "r"(mbar), "r"(bytes) : "memory");
}
__device__ __forceinline__ void mbar_arrive(unsigned mbar) {
    asm volatile("mbarrier.arrive.shared.b64 _, [%0];" :: "r"(mbar) : "memory");
}
__device__ __forceinline__ void mbar_wait(unsigned mbar, unsigned phase) {
    asm volatile(
        "{\n\t.reg .pred P1;\n\t"
        "LAB_WAIT_%=:\n\t"
        "mbarrier.try_wait.parity.shared.b64 P1, [%0], %1;\n\t"
        "@P1 bra.uni DONE_%=;\n\t"
        "bra.uni LAB_WAIT_%=;\n\t"
        "DONE_%=:\n\t}"
        :: "r"(mbar), "r"(phase) : "memory");
}
__device__ __forceinline__ void bulk_g2s(unsigned dst, const void* src, unsigned bytes, unsigned mbar) {
    asm volatile("cp.async.bulk.shared::cluster.global.mbarrier::complete_tx::bytes [%0], [%1], %2, [%3];"
                 :: "r"(dst), "l"(src), "r"(bytes), "r"(mbar) : "memory");
}
__device__ __forceinline__ void bar_compute() {   // compute warps only (256 threads)
    asm volatile("bar.sync 1, 256;" ::: "memory");
}

// init-time grid barrier (atomic; used once per launch)
__device__ __forceinline__ void gridbar()
{
    __syncthreads();
    if (threadIdx.x == 0) {
        __threadfence();
        volatile unsigned* gen = &g_gen;
        unsigned g0 = *gen;
        unsigned arr = atomicAdd(&g_cnt, 1u);
        if (arr == NCTA_REC - 1) {
            g_cnt = 0;
            __threadfence();
            *gen = g0 + 1u;
        } else {
            while (*gen == g0) { }
        }
    }
    __syncthreads();
    __threadfence();
}

// ======================================================================
// Kernel 0: one-time f32 -> bf16 conversion of emb and the 4 input weights
// ======================================================================
__global__ __launch_bounds__(256) void k_convert(
    const float* __restrict__ emb,
    const float* __restrict__ W0, const float* __restrict__ W1,
    const float* __restrict__ W2, const float* __restrict__ W3)
{
    const float* Wsrc[4] = { W0, W1, W2, W3 };
    size_t tid    = (size_t)blockIdx.x * blockDim.x + threadIdx.x;
    size_t stride = (size_t)gridDim.x * blockDim.x;
    const size_t nW4 = (size_t)DD * HH / 4;
    for (size_t e = tid; e < 4 * nW4; e += stride) {
        int g = (int)(e / nW4);
        size_t o = (e % nW4) * 4;
        float4 v = *(const float4*)(Wsrc[g] + o);
        __nv_bfloat16* d = &g_Wxb[g][o];
        d[0] = __float2bfloat16(v.x); d[1] = __float2bfloat16(v.y);
        d[2] = __float2bfloat16(v.z); d[3] = __float2bfloat16(v.w);
    }
    const size_t nE4 = (size_t)(NCC + 1) * DD / 4;
    for (size_t e = tid; e < nE4; e += stride) {
        float4 v = *(const float4*)(emb + e * 4);
        __nv_bfloat16* d = &g_embb[e * 4];
        d[0] = __float2bfloat16(v.x); d[1] = __float2bfloat16(v.y);
        d[2] = __float2bfloat16(v.z); d[3] = __float2bfloat16(v.w);
    }
}

// ======================================================================
// Kernel 1: input projections (double-buffered cp.async + wmma) — R5 best
// ======================================================================
#define AS_LD 56
#define BS_LD 152

__global__ __launch_bounds__(256) void k_input_proj(const int* __restrict__ x)
{
    __shared__ __align__(16) __nv_bfloat16 As[2][128 * AS_LD];
    __shared__ __align__(16) __nv_bfloat16 Bs[2][32 * BS_LD];
    __shared__ int rowidx[128];

    const int t = threadIdx.x, w = t >> 5;
    const int tn = blockIdx.x, tm = blockIdx.y;
    const int n0 = tn * 128, gate = n0 >> 10, h0 = n0 & 1023;
    const __nv_bfloat16* Wb = g_Wxb[gate];

    if (t < 128) {
        int m = tm * 128 + t;
        int s = m >> 7, b = m & 127;
        rowidx[t] = x[b * SS + s];
    }
    __syncthreads();

    auto issue = [&](int it) {
        int kt = it * 32;
        unsigned int Aa = (unsigned int)__cvta_generic_to_shared(As[it & 1]);
        unsigned int Ba = (unsigned int)__cvta_generic_to_shared(Bs[it & 1]);
#pragma unroll
        for (int i = 0; i < 2; i++) {
            int e = t + i * 256, r = e >> 2, seg = e & 3;
            cp16(Aa + (r * AS_LD + seg * 8) * 2,
                 g_embb + (size_t)rowidx[r] * DD + kt + seg * 8);
        }
#pragma unroll
        for (int i = 0; i < 2; i++) {
            int e = t + i * 256, r = e >> 4, seg = e & 15;
            cp16(Ba + (r * BS_LD + seg * 8) * 2,
                 Wb + (size_t)(kt + r) * HH + h0 + seg * 8);
        }
    };

    wmma::fragment<wmma::accumulator, 16, 16, 16, float> acc[8];
#pragma unroll
    for (int i = 0; i < 8; i++) wmma::fill_fragment(acc[i], 0.0f);

    issue(0); cp_commit();
    for (int it = 0; it < 16; it++) {
        if (it < 15) issue(it + 1);
        cp_commit();
        cp_wait<1>();
        __syncthreads();
        const __nv_bfloat16* A = As[it & 1];
        const __nv_bfloat16* B = Bs[it & 1];
#pragma unroll
        for (int ks = 0; ks < 2; ks++) {
            wmma::fragment<wmma::matrix_a, 16, 16, 16, __nv_bfloat16, wmma::row_major> af;
            wmma::load_matrix_sync(af, A + (w * 16) * AS_LD + ks * 16, AS_LD);
#pragma unroll
            for (int nb = 0; nb < 8; nb++) {
                wmma::fragment<wmma::matrix_b, 16, 16, 16, __nv_bfloat16, wmma::row_major> bfr;
                wmma::load_matrix_sync(bfr, B + (ks * 16) * BS_LD + nb * 16, BS_LD);
                wmma::mma_sync(acc[nb], af, bfr, acc[nb]);
            }
        }
        __syncthreads();
    }

    size_t base = (size_t)(tm * 128 + w * 16) * 4096 + n0;
#pragma unroll
    for (int nb = 0; nb < 8; nb++)
        wmma::store_matrix_sync(g_P + base + nb * 16, acc[nb], 4096, wmma::mem_row_major);
}

// ======================================================================
// Kernel 2: persistent recurrent scan, warp-specialized.
// 288 threads: warps 0-7 = mma consumers (R5 layout, m=16/warp, N=32);
// warp 8 = TMA producer running a free ring over 2048 chunk fills
// (8 x 32KB chunks/step, 4 buffers, full/empty mbarriers),
// gated by 8 per-chunk cross-CTA counters (16 producers each).
// No per-step grid barrier.
// ======================================================================
#define WS_LD 1032
#define CHUNK_B 32768

#define SM_MBAR   0      // full[4] @0..31, empty[4] @32..63
#define SM_ABUF   1024
#define SM_WS     (SM_ABUF + 4 * CHUNK_B)      // 132096
#define SM_SG     (SM_WS + 32 * WS_LD * 2)     // 198144
#define SM_TOT    (SM_SG + 128 * 36 * 4)       // 216576

__global__ void __launch_bounds__(288, 1) k_recur(
    const int*   __restrict__ x,
    const float* __restrict__ Wfh, const float* __restrict__ Wih,
    const float* __restrict__ Wgh, const float* __restrict__ Woh,
    const float* __restrict__ bfp, const float* __restrict__ bip,
    const float* __restrict__ bgp, const float* __restrict__ bop)
{
    extern __shared__ __align__(1024) unsigned char dyn[];
    __nv_bfloat16* Ws = (__nv_bfloat16*)(dyn + SM_WS);
    float*         Sg = (float*)(dyn + SM_SG);

    const unsigned smem0 = (unsigned)__cvta_generic_to_shared(dyn);
    unsigned mbF[4], mbE[4], Abuf[4];
#pragma unroll
    for (int i = 0; i < 4; i++) {
        mbF[i]  = smem0 + SM_MBAR + i * 8;
        mbE[i]  = smem0 + SM_MBAR + 32 + i * 8;
        Abuf[i] = smem0 + SM_ABUF + i * CHUNK_B;
    }

    const int t = threadIdx.x, w = t >> 5, l = t & 31;
    const int c = blockIdx.x, u0 = c * 8;
    const int grp = c >> 4;                    // h-chunk this CTA produces (16 CTAs/chunk)
    const float* Wg[4] = { Wfh, Wih, Wgh, Woh };

    if (t == 0) {
#pragma unroll
        for (int i = 0; i < 4; i++) { mbar_init(mbF[i], 1); mbar_init(mbE[i], 8); }
    }
    asm volatile("fence.proxy.async.shared::cta;" ::: "memory");

    // counter bases (monotonic across replays; read before init gridbar)
    unsigned fb[8];
#pragma unroll
    for (int i = 0; i < 8; i++) fb[i] = *(volatile unsigned*)&g_chk[i * 32];

    // weight slice -> SMEM (bf16, col-major, padded stride)
    for (int e = t; e < 32 * 1024; e += 288) {
        int k = e >> 5, col = e & 31, g = col >> 3, j = col & 7;
        Ws[col * WS_LD + k] = __float2bfloat16(Wg[g][(size_t)k * HH + u0 + j]);
    }
    // zero own 8 rows of hT buffer 0 (8 rows x 256B; 256 threads x 8B)
    if (t < 256)
        *(unsigned long long*)(g_hT2[0] + (u0 + (t >> 5)) * 256 + (t & 31) * 8) = 0ull;

    // epilogue mapping: b = t>>1, units u0+jq..+3 (threads 0..255)
    const int eb = (t < 256) ? (t >> 1) : 0;
    const int jq = (t & 1) * 4;
    float4 bias0, bias1, bias2, bias3;
    if (t < 256) {
        bias0 = *(const float4*)(bfp + u0 + jq);
        bias1 = *(const float4*)(bip + u0 + jq);
        bias2 = *(const float4*)(bgp + u0 + jq);
        bias3 = *(const float4*)(bop + u0 + jq);
    }
    float C0 = 0.f, C1 = 0.f, C2 = 0.f, C3 = 0.f;

    // ldmatrix lane constants (warps 0-7)
    const unsigned a_sw   = (((unsigned)(2 * w + ((l >> 3) & 1)) ^ (unsigned)(l & 7)) << 4);
    const int      a_krow = (l & 7) + ((l >> 4) & 1) * 8;
    const unsigned bbase  = smem0 + SM_WS + ((l & 7) + ((l >> 4) & 1) * 8) * (WS_LD * 2) + ((l >> 3) & 1) * 16;

    const unsigned blo = (unsigned)(eb & 7) * 2, bhi = (unsigned)(eb >> 3);

    __syncthreads();
    gridbar();   // zeros + SMEM + mbarriers + counter bases consistent everywhere

    if (t >= 256) {
        // ---------------- producer warp ----------------
        if (t == 256) {
            unsigned q = 0;
            for (int s = 0; s < SS; s++) {
                const unsigned char* hsrc = g_hT2[s & 1];
                const unsigned lvl = (unsigned)s * 16u;
                for (int cc = 0; cc < 8; cc++, q++) {
                    const int b = q & 3;
                    const unsigned j = q >> 2;
                    if (j) mbar_wait(mbE[b], (j - 1) & 1);    // buffer free
                    if (s) {                                   // producers of chunk cc done step s-1
                        unsigned tgt = fb[cc] + lvl;
                        while ((int)(ld_acq(&g_chk[cc * 32]) - tgt) < 0) { }
                    }
                    mbar_expect(mbF[b], CHUNK_B);
                    bulk_g2s(Abuf[b], hsrc + cc * CHUNK_B, CHUNK_B, mbF[b]);
                }
            }
        }
    } else {
        // ---------------- compute warps (0-7) ----------------
        unsigned q = 0;
        for (int s = 0; s < SS; s++) {
            unsigned char* hdst = g_hT2[(s + 1) & 1];

            // prefetch input-side preacts + reset mask
            const float* Pb = g_P + ((size_t)(s * BB + eb)) * 4096 + (u0 + jq);
            float4 pf0 = *(const float4*)(Pb);
            float4 pf1 = *(const float4*)(Pb + 1024);
            float4 pf2 = *(const float4*)(Pb + 2048);
            float4 pf3 = *(const float4*)(Pb + 3072);
            const float rmask = (x[eb * SS + s] > 0) ? 1.0f : 0.0f;

            float acc[16];
#pragma unroll
            for (int i = 0; i < 16; i++) acc[i] = 0.0f;

            for (int cc = 0; cc < 8; cc++, q++) {
                const int b = q & 3;
                mbar_wait(mbF[b], (q >> 2) & 1);
                const unsigned Ab = Abuf[b];
#pragma unroll
                for (int kt = 0; kt < 8; kt++) {
                    unsigned aaddr = Ab + (unsigned)((kt * 16 + a_krow) * 256) + a_sw;
                    unsigned a0, a1, a2, a3;
                    asm volatile("ldmatrix.sync.aligned.m8n8.x4.trans.shared.b16 {%0,%1,%2,%3}, [%4];"
                                 : "=r"(a0), "=r"(a1), "=r"(a2), "=r"(a3) : "r"(aaddr));
                    unsigned baddr = bbase + (unsigned)((cc * 8 + kt) * 32);
                    unsigned b0, b1, b2, b3, b4, b5, b6, b7;
                    asm volatile("ldmatrix.sync.aligned.m8n8.x4.shared.b16 {%0,%1,%2,%3}, [%4];"
                                 : "=r"(b0), "=r"(b1), "=r"(b2), "=r"(b3) : "r"(baddr));
                    asm volatile("ldmatrix.sync.aligned.m8n8.x4.shared.b16 {%0,%1,%2,%3}, [%4];"
                                 : "=r"(b4), "=r"(b5), "=r"(b6), "=r"(b7) : "r"(baddr + 16u * (WS_LD * 2)));

#define MMA4(O, B0, B1) \
                    asm volatile("mma.sync.aligned.m16n8k16.row.col.f32.bf16.bf16.f32 " \
                                 "{%0,%1,%2,%3}, {%4,%5,%6,%7}, {%8,%9}, {%0,%1,%2,%3};" \
                                 : "+f"(acc[O]), "+f"(acc[O+1]), "+f"(acc[O+2]), "+f"(acc[O+3]) \
                                 : "r"(a0), "r"(a1), "r"(a2), "r"(a3), "r"(B0), "r"(B1))
                    MMA4(0,  b0, b1);
                    MMA4(4,  b2, b3);
                    MMA4(8,  b4, b5);
                    MMA4(12, b6, b7);
#undef MMA4
                }
                if (l == 0) mbar_arrive(mbE[b]);   // warp done reading buffer b
            }

            // store C-fragments to Sg [128 m][36 stride]
            {
                int mr = w * 16 + (l >> 2);
                int col = 2 * (l & 3);
#pragma unroll
                for (int nt = 0; nt < 4; nt++) {
                    *(float2*)&Sg[mr * 36 + nt * 8 + col]       = make_float2(acc[nt * 4 + 0], acc[nt * 4 + 1]);
                    *(float2*)&Sg[(mr + 8) * 36 + nt * 8 + col] = make_float2(acc[nt * 4 + 2], acc[nt * 4 + 3]);
                }
            }
            bar_compute();

            // gate epilogue: thread handles (b=eb, units u0+jq..+3)
            {
                float4 S0 = *(float4*)&Sg[eb * 36 +  0 + jq];
                float4 S1 = *(float4*)&Sg[eb * 36 +  8 + jq];
                float4 S2 = *(float4*)&Sg[eb * 36 + 16 + jq];
                float4 S3 = *(float4*)&Sg[eb * 36 + 24 + jq];

                float f0 = sigm(pf0.x + bias0.x + S0.x), f1 = sigm(pf0.y + bias0.y + S0.y);
                float f2 = sigm(pf0.z + bias0.z + S0.z), f3 = sigm(pf0.w + bias0.w + S0.w);
                float i0 = sigm(pf1.x + bias1.x + S1.x), i1 = sigm(pf1.y + bias1.y + S1.y);
                float i2 = sigm(pf1.z + bias1.z + S1.z), i3 = sigm(pf1.w + bias1.w + S1.w);
                float g0 = sigm(pf2.x + bias2.x + S2.x), g1 = sigm(pf2.y + bias2.y + S2.y);
                float g2 = sigm(pf2.z + bias2.z + S2.z), g3 = sigm(pf2.w + bias2.w + S2.w);
                float o0 = sigm(pf3.x + bias3.x + S3.x), o1 = sigm(pf3.y + bias3.y + S3.y);
                float o2 = sigm(pf3.z + bias3.z + S3.z), o3 = sigm(pf3.w + bias3.w + S3.w);

                C0 = (g0 * i0 + C0 * f0) * rmask;
                C1 = (g1 * i1 + C1 * f1) * rmask;
                C2 = (g2 * i2 + C2 * f2) * rmask;
                C3 = (g3 * i3 + C3 * f3) * rmask;
                float h0v = o0 * tanhf(C0), h1v = o1 * tanhf(C1);
                float h2v = o2 * tanhf(C2), h3v = o3 * tanhf(C3);

#pragma unroll
                for (int i = 0; i < 4; i++) {
                    float hv = (i == 0) ? h0v : (i == 1) ? h1v : (i == 2) ? h2v : h3v;
                    unsigned u = (unsigned)(u0 + jq + i);
                    *(__nv_bfloat16*)(hdst + u * 256 + ((bhi ^ (u & 7)) << 4) + blo) = __float2bfloat16(hv);
                }
                if (s == SS - 1) {
                    *(float2*)(g_hf + eb * HH + u0 + jq)     = make_float2(h0v, h1v);
                    *(float2*)(g_hf + eb * HH + u0 + jq + 2) = make_float2(h2v, h3v);
                }
            }

            bar_compute();   // all STG h + Sg reads done
            if (t == 0 && s < SS - 1) {
                __threadfence();
                atomicAdd(&g_chk[grp * 32], 1u);   // publish own chunk of step s+1
            }
        }
    }
}

// ======================================================================
// Kernel 3: logits + log_softmax (256 thr, split-K x2, 4 accums — R5 best)
// ======================================================================
__global__ __launch_bounds__(256) void k_final(
    const float* __restrict__ Wph, const float* __restrict__ bp,
    float* __restrict__ out)
{
    __shared__ float h[HH];
    __shared__ float part[NCC];
    __shared__ float red[NCC];
    const int b = blockIdx.x, t = threadIdx.x;
    const int cls = t & 127, half = t >> 7;

    for (int i = t; i < HH; i += 256) h[i] = g_hf[b * HH + i];
    __syncthreads();

    const float* W = Wph + (size_t)(half * 512) * NCC + cls;
    const float* hh = h + half * 512;
    float a0 = 0.f, a1 = 0.f, a2 = 0.f, a3 = 0.f;
#pragma unroll 8
    for (int k = 0; k < 512; k += 4) {
        a0 += hh[k + 0] * W[(size_t)(k + 0) * NCC];
        a1 += hh[k + 1] * W[(size_t)(k + 1) * NCC];
        a2 += hh[k + 2] * W[(size_t)(k + 2) * NCC];
        a3 += hh[k + 3] * W[(size_t)(k + 3) * NCC];
    }
    float p = (a0 + a1) + (a2 + a3);
    if (half) part[cls] = p;
    __syncthreads();

    if (half == 0) p += part[cls] + bp[cls];

    if (t < 128) red[t] = p;
    __syncthreads();
    for (int off = 64; off; off >>= 1) {
        if (t < off) red[t] = fmaxf(red[t], red[t + off]);
        __syncthreads();
    }
    float m = red[0]; __syncthreads();
    if (t < 128) red[t] = expf(p - m);
    __syncthreads();
    for (int off = 64; off; off >>= 1) {
        if (t < off) red[t] += red[t + off];
        __syncthreads();
    }
    if (t < 128) {
        float lse = m + logf(red[0]);
        out[b * NCC + t] = p - lse;
    }
}

// ======================================================================
extern "C" void kernel_launch(void* const* d_in, const int* in_sizes, int n_in,
                              void* d_out, int out_size)
{
    const int*   x   = (const int*)  d_in[0];
    const float* emb = (const float*)d_in[1];
    const float* Wfx = (const float*)d_in[2];
    const float* Wfh = (const float*)d_in[3];
    const float* bf  = (const float*)d_in[4];
    const float* Wix = (const float*)d_in[5];
    const float* Wih = (const float*)d_in[6];
    const float* bi  = (const float*)d_in[7];
    const float* Wgx = (const float*)d_in[8];
    const float* Wgh = (const float*)d_in[9];
    const float* bg  = (const float*)d_in[10];
    const float* Wox = (const float*)d_in[11];
    const float* Woh = (const float*)d_in[12];
    const float* bo  = (const float*)d_in[13];
    const float* Wph = (const float*)d_in[14];
    const float* bp  = (const float*)d_in[15];
    float* out = (float*)d_out;

    static bool attr_set = false;
    if (!attr_set) {
        cudaFuncSetAttribute(k_recur, cudaFuncAttributeMaxDynamicSharedMemorySize, SM_TOT);
        attr_set = true;
    }

    // 0) bf16 pre-conversion
    k_convert<<<512, 256>>>(emb, Wfx, Wix, Wgx, Wox);

    // 1) input-side projections
    dim3 g1(4096 / 128, (SS * BB) / 128);
    k_input_proj<<<g1, 256>>>(x);

    // 2) persistent recurrent scan (warp-specialized producer)
    k_recur<<<NCTA_REC, 288, SM_TOT>>>(x, Wfh, Wih, Wgh, Woh, bf, bi, bg, bo);

    // 3) final projection + log_softmax
    k_final<<<BB, 256>>>(Wph, bp, out);
}